// round 1
// baseline (speedup 1.0000x reference)
#include <cuda_runtime.h>
#include <cuda_bf16.h>
#include <mma.h>
#include <cstdint>
#include <math.h>

using namespace nvcuda;

#define NN 8192
#define DD 768
#define BM 64
#define BN 64
#define BK 64
#define CPB 1024                 // columns handled per block
#define CSPLITS (NN / CPB)       // 8
#define RTILES  (NN / BM)        // 128
#define CS_LD 72                 // padded ld for C tile in smem (mult of 4)
#define NEG_BIG (-1.0e30f)

// Scratch (no allocations allowed) -------------------------------------------
__device__ __nv_bfloat16 g_xb[NN * DD];          // bf16 copy of x (12 MB)
__device__ float g_sq[NN];                       // row squared norms (f32)
__device__ float g_pm[NN * CSPLITS];             // partial max
__device__ float g_pz[NN * CSPLITS];             // partial Z
__device__ float g_pt[NN * CSPLITS];             // partial T = sum (l-m)e^(l-m)

// Merge two (m, Z, T) softmax-stat triples. No clamps: __expf of very negative
// finite values returns exactly 0, preserving exact-zero entropy like the ref.
__device__ __forceinline__ void merge_stats(float& m, float& z, float& t,
                                            float m2, float z2, float t2) {
    float mn = fmaxf(m, m2);
    float d1 = m - mn, d2 = m2 - mn;   // finite (inits are -1e30, not -inf)
    float a = __expf(d1), b = __expf(d2);
    t = a * (t + d1 * z) + b * (t2 + d2 * z2);
    z = a * z + b * z2;
    m = mn;
}

// Kernel 1: convert x -> bf16, compute sq[i] = sum_k x[i,k]^2 (f32)
__global__ void prep_kernel(const float* __restrict__ x) {
    int row = blockIdx.x;
    const float* xr = x + (size_t)row * DD;
    __nv_bfloat16* xb = g_xb + (size_t)row * DD;
    float s = 0.f;
#pragma unroll
    for (int it = 0; it < DD / 256; ++it) {
        int k = threadIdx.x + it * 256;
        float v = xr[k];
        s += v * v;
        xb[k] = __float2bfloat16(v);
    }
#pragma unroll
    for (int o = 16; o > 0; o >>= 1) s += __shfl_down_sync(0xffffffffu, s, o);
    __shared__ float ws[8];
    int wid = threadIdx.x >> 5, lane = threadIdx.x & 31;
    if (lane == 0) ws[wid] = s;
    __syncthreads();
    if (threadIdx.x == 0) {
        float tot = 0.f;
#pragma unroll
        for (int i = 0; i < 8; ++i) tot += ws[i];
        g_sq[row] = tot;
    }
}

// Kernel 2: fused Gram (bf16 wmma) + online softmax-entropy stats.
// Grid: (CSPLITS, RTILES). Block: 256 threads = 8 warps in 4x2 (warp_m, warp_n).
// A tile (64 rows x 768) resident in smem; B staged 64x64 double-buffered.
__global__ __launch_bounds__(256, 1)
void main_kernel(const float* __restrict__ tau_p) {
    extern __shared__ char smem_raw[];
    __nv_bfloat16* As = reinterpret_cast<__nv_bfloat16*>(smem_raw);                       // [BM][DD]
    __nv_bfloat16* Bs = reinterpret_cast<__nv_bfloat16*>(smem_raw + BM * DD * 2);         // [2][BN][BK]
    float* Cs = reinterpret_cast<float*>(smem_raw + BM * DD * 2 + 2 * BN * BK * 2);       // [BM][CS_LD]
    float* rm = Cs + BM * CS_LD;
    float* rz = rm + BM;
    float* rt = rz + BM;

    const float tau = *tau_p;
    const int rowbase  = blockIdx.y * BM;
    const int colbase0 = blockIdx.x * CPB;
    const int tid = threadIdx.x;
    const int wid = tid >> 5;
    const int warp_m = wid >> 1;   // 0..3 -> 16-row strip
    const int warp_n = wid & 1;    // 0..1 -> 32-col strip

    // Load resident A tile (bf16), vectorized 16B
    {
        const uint4* src = reinterpret_cast<const uint4*>(g_xb + (size_t)rowbase * DD);
        uint4* dst = reinterpret_cast<uint4*>(As);
#pragma unroll
        for (int i = 0; i < (BM * DD / 8) / 256; ++i)
            dst[tid + i * 256] = src[tid + i * 256];
    }
    if (tid < BM) { rm[tid] = NEG_BIG; rz[tid] = 0.f; rt[tid] = 0.f; }
    __syncthreads();

    wmma::fragment<wmma::matrix_a, 16, 16, 16, __nv_bfloat16, wmma::row_major> af;
    wmma::fragment<wmma::matrix_b, 16, 16, 16, __nv_bfloat16, wmma::col_major> bf0, bf1;

    const int r = tid >> 2;   // row within tile (0..63)
    const int q = tid & 3;    // 16-col chunk within tile

    for (int ct = 0; ct < CPB / BN; ++ct) {
        const int colbase = colbase0 + ct * BN;
        wmma::fragment<wmma::accumulator, 16, 16, 16, float> c0, c1;
        wmma::fill_fragment(c0, 0.0f);
        wmma::fill_fragment(c1, 0.0f);

        const uint4* bsrc = reinterpret_cast<const uint4*>(g_xb + (size_t)colbase * DD);
        // Preload k-chunk 0 into stage 0
#pragma unroll
        for (int i = 0; i < 2; ++i) {
            int idx = tid + i * 256;               // idx = brow*8 + bcol
            int brow = idx >> 3, bcol = idx & 7;
            reinterpret_cast<uint4*>(Bs)[idx] = bsrc[brow * (DD / 8) + bcol];
        }
        __syncthreads();

#pragma unroll 1
        for (int kc = 0; kc < DD / BK; ++kc) {
            const int cur = kc & 1;
            uint4 pre[2];
            const bool has_next = (kc + 1 < DD / BK);
            if (has_next) {
#pragma unroll
                for (int i = 0; i < 2; ++i) {
                    int idx = tid + i * 256;
                    int brow = idx >> 3, bcol = idx & 7;
                    pre[i] = bsrc[brow * (DD / 8) + (kc + 1) * 8 + bcol];
                }
            }
            const __nv_bfloat16* Bcur = Bs + cur * (BN * BK);
#pragma unroll
            for (int kk = 0; kk < BK; kk += 16) {
                wmma::load_matrix_sync(af, As + (warp_m * 16) * DD + kc * BK + kk, DD);
                wmma::load_matrix_sync(bf0, Bcur + (warp_n * 32) * BK + kk, BK);
                wmma::load_matrix_sync(bf1, Bcur + (warp_n * 32 + 16) * BK + kk, BK);
                wmma::mma_sync(c0, af, bf0, c0);
                wmma::mma_sync(c1, af, bf1, c1);
            }
            if (has_next) {
                uint4* dst = reinterpret_cast<uint4*>(Bs + (cur ^ 1) * (BN * BK));
#pragma unroll
                for (int i = 0; i < 2; ++i) dst[tid + i * 256] = pre[i];
            }
            __syncthreads();
        }

        // Spill C tile to smem to get a defined layout for the epilogue
        wmma::store_matrix_sync(Cs + (warp_m * 16) * CS_LD + warp_n * 32,      c0, CS_LD, wmma::mem_row_major);
        wmma::store_matrix_sync(Cs + (warp_m * 16) * CS_LD + warp_n * 32 + 16, c1, CS_LD, wmma::mem_row_major);
        __syncthreads();

        // Epilogue: logits l = tau*(2g - sq_j - 100*[i==j]) (per-row const sq_i
        // dropped: entropy is shift-invariant). Online (m,Z,T) update.
        {
            const int grow = rowbase + r;
            float v[16];
            float mloc = NEG_BIG;
#pragma unroll
            for (int j = 0; j < 16; ++j) {
                int col = q * 16 + j;
                int gcol = colbase + col;
                float g = Cs[r * CS_LD + col];
                float l = tau * (2.0f * g - g_sq[gcol] - ((gcol == grow) ? 100.0f : 0.0f));
                v[j] = l;
                mloc = fmaxf(mloc, l);
            }
            float zloc = 0.f, tloc = 0.f;
#pragma unroll
            for (int j = 0; j < 16; ++j) {
                float d = v[j] - mloc;
                float e = __expf(d);
                zloc += e;
                tloc += d * e;
            }
            // merge the 4 chunks of this row (lanes 4r..4r+3, xor stays in-group)
#pragma unroll
            for (int o = 1; o < 4; o <<= 1) {
                float mo = __shfl_xor_sync(0xffffffffu, mloc, o);
                float zo = __shfl_xor_sync(0xffffffffu, zloc, o);
                float to = __shfl_xor_sync(0xffffffffu, tloc, o);
                merge_stats(mloc, zloc, tloc, mo, zo, to);
            }
            if (q == 0) {   // unique writer per row
                float m = rm[r], z = rz[r], t = rt[r];
                merge_stats(m, z, t, mloc, zloc, tloc);
                rm[r] = m; rz[r] = z; rt[r] = t;
            }
        }
        __syncthreads();
    }

    if (tid < BM) {
        int grow = rowbase + tid;
        g_pm[grow * CSPLITS + blockIdx.x] = rm[tid];
        g_pz[grow * CSPLITS + blockIdx.x] = rz[tid];
        g_pt[grow * CSPLITS + blockIdx.x] = rt[tid];
    }
}

// Kernel 3: merge column-split partials per row -> entropy; mean; scale by coef
__global__ void finalize_kernel(const float* __restrict__ coef_p, float* __restrict__ out) {
    const int tid = threadIdx.x;
    float acc = 0.f;
    for (int rr = tid; rr < NN; rr += 1024) {
        float m = NEG_BIG, z = 0.f, t = 0.f;
#pragma unroll
        for (int s = 0; s < CSPLITS; ++s)
            merge_stats(m, z, t,
                        g_pm[rr * CSPLITS + s],
                        g_pz[rr * CSPLITS + s],
                        g_pt[rr * CSPLITS + s]);
        acc += logf(z) - t / z;   // H = log Z' - T/Z'
    }
#pragma unroll
    for (int o = 16; o > 0; o >>= 1) acc += __shfl_down_sync(0xffffffffu, acc, o);
    __shared__ float ws[32];
    int wid = tid >> 5, lane = tid & 31;
    if (lane == 0) ws[wid] = acc;
    __syncthreads();
    if (tid == 0) {
        float tot = 0.f;
#pragma unroll
        for (int i = 0; i < 32; ++i) tot += ws[i];
        out[0] = coef_p[0] * (tot / (float)NN);
    }
}

extern "C" void kernel_launch(void* const* d_in, const int* in_sizes, int n_in,
                              void* d_out, int out_size) {
    (void)in_sizes; (void)n_in; (void)out_size;
    const float* x    = (const float*)d_in[0];
    const float* coef = (const float*)d_in[1];
    const float* tau  = (const float*)d_in[2];
    float* out = (float*)d_out;

    prep_kernel<<<NN, 256>>>(x);

    constexpr int SMEM_BYTES = BM * DD * 2 + 2 * BN * BK * 2 + BM * CS_LD * 4 + 3 * BM * 4;
    cudaFuncSetAttribute(main_kernel, cudaFuncAttributeMaxDynamicSharedMemorySize, SMEM_BYTES);
    main_kernel<<<dim3(CSPLITS, RTILES), 256, SMEM_BYTES>>>(tau);

    finalize_kernel<<<1, 1024>>>(coef, out);
}

// round 3
// speedup vs baseline: 3.4772x; 3.4772x over previous
#include <cuda_runtime.h>
#include <cuda_bf16.h>
#include <cstdint>
#include <math.h>

// ---------------------------------------------------------------------------
#define NN 8192
#define DD 768
#define BM 128                   // CTA tile rows
#define BN 256                   // CTA tile cols
#define BK 32                    // k per pipeline chunk (64B per row)
#define NCH (DD / BK)            // 24 k-chunks
#define STAGES 4
#define STAGE_BYTES 24576        // A 128*64B + B 256*64B
#define SMEM_TOTAL (STAGES * STAGE_BYTES)   // 96 KB
#define NP (NN / BN)             // 32 column partials per row
#define NEG_BIG (-1.0e30f)

// Scratch (no allocations allowed)
__device__ __align__(256) __nv_bfloat16 g_xb[NN * DD];   // bf16 X (12 MB)
__device__ float g_sq[NN];
__device__ float g_pm[NN * NP];
__device__ float g_pz[NN * NP];
__device__ float g_pt[NN * NP];

// ---------------------------------------------------------------------------
__device__ __forceinline__ uint32_t smem_u32(const void* p) {
    uint32_t a;
    asm("{ .reg .u64 t; cvta.to.shared.u64 t, %1; cvt.u32.u64 %0, t; }" : "=r"(a) : "l"(p));
    return a;
}
// 64B-row swizzle: bits[5:4] ^= row bits[2:1]  (row = off>>6)
__device__ __forceinline__ uint32_t sw64(uint32_t off) {
    return off ^ (((off >> 7) & 3u) << 4);
}
__device__ __forceinline__ void cp_async16(uint32_t dst, const void* src) {
    asm volatile("cp.async.cg.shared.global [%0], [%1], 16;" :: "r"(dst), "l"(src) : "memory");
}
#define CP_COMMIT() asm volatile("cp.async.commit_group;" ::: "memory")
#define CP_WAIT2()  asm volatile("cp.async.wait_group 2;" ::: "memory")
#define CP_WAIT0()  asm volatile("cp.async.wait_group 0;" ::: "memory")

__device__ __forceinline__ void ldsm_x4(uint32_t& r0, uint32_t& r1, uint32_t& r2, uint32_t& r3,
                                        uint32_t addr) {
    asm volatile("ldmatrix.sync.aligned.m8n8.x4.shared.b16 {%0,%1,%2,%3}, [%4];"
                 : "=r"(r0), "=r"(r1), "=r"(r2), "=r"(r3) : "r"(addr));
}
__device__ __forceinline__ void mma16816(float* d, const uint32_t* a, uint32_t b0, uint32_t b1) {
    asm volatile(
        "mma.sync.aligned.m16n8k16.row.col.f32.bf16.bf16.f32 "
        "{%0,%1,%2,%3}, {%4,%5,%6,%7}, {%8,%9}, {%0,%1,%2,%3};"
        : "+f"(d[0]), "+f"(d[1]), "+f"(d[2]), "+f"(d[3])
        : "r"(a[0]), "r"(a[1]), "r"(a[2]), "r"(a[3]), "r"(b0), "r"(b1));
}
__device__ __forceinline__ void merge_stats(float& m, float& z, float& t,
                                            float m2, float z2, float t2) {
    float mn = fmaxf(m, m2);
    float d1 = m - mn, d2 = m2 - mn;
    float a = __expf(d1), b = __expf(d2);
    t = a * (t + d1 * z) + b * (t2 + d2 * z2);
    z = a * z + b * z2;
    m = mn;
}

// ---------------------------------------------------------------------------
// Kernel 1: f32 -> bf16 convert + row squared norms. 192 threads = one row.
__global__ void prep_kernel(const float* __restrict__ x) {
    int row = blockIdx.x;
    int t = threadIdx.x;
    float4 v = reinterpret_cast<const float4*>(x + (size_t)row * DD)[t];
    float s = v.x * v.x + v.y * v.y + v.z * v.z + v.w * v.w;
    __nv_bfloat162 p0, p1;
    p0.x = __float2bfloat16(v.x); p0.y = __float2bfloat16(v.y);
    p1.x = __float2bfloat16(v.z); p1.y = __float2bfloat16(v.w);
    __nv_bfloat162* dst = reinterpret_cast<__nv_bfloat162*>(g_xb + (size_t)row * DD);
    dst[2 * t] = p0;
    dst[2 * t + 1] = p1;
#pragma unroll
    for (int o = 16; o > 0; o >>= 1) s += __shfl_down_sync(0xffffffffu, s, o);
    __shared__ float ws[6];
    int wid = t >> 5, lane = t & 31;
    if (lane == 0) ws[wid] = s;
    __syncthreads();
    if (t == 0) {
        float tot = 0.f;
#pragma unroll
        for (int i = 0; i < 6; ++i) tot += ws[i];
        g_sq[row] = tot;
    }
}

// ---------------------------------------------------------------------------
// Stage fill: A tile 128x32 (rowbase), B tile 256x32 (colbase), 512 threads.
__device__ __forceinline__ void fill_stage(uint32_t sbase, int kc, int rowbase,
                                           int colbase, int tid) {
    const int r  = tid >> 2;            // 0..127
    const int c4 = tid & 3;             // 16B segment within 64B row
    const __nv_bfloat16* __restrict__ xb = g_xb;
    // A: rows rowbase..+127
    cp_async16(sbase + sw64((uint32_t)(r * 64 + c4 * 16)),
               xb + (size_t)(rowbase + r) * DD + kc * BK + c4 * 8);
    // B: rows colbase..+255 (two halves)
    const uint32_t bbase = sbase + 8192;
    cp_async16(bbase + sw64((uint32_t)(r * 64 + c4 * 16)),
               xb + (size_t)(colbase + r) * DD + kc * BK + c4 * 8);
    cp_async16(bbase + sw64((uint32_t)((r + 128) * 64 + c4 * 16)),
               xb + (size_t)(colbase + r + 128) * DD + kc * BK + c4 * 8);
}

// ---------------------------------------------------------------------------
// Kernel 2: pipelined bf16 HMMA Gram + fused online softmax-entropy stats.
// 512 threads = 16 warps in 4(m) x 4(n); warp tile 32x64.
__global__ __launch_bounds__(512, 1)
void main_kernel(const float* __restrict__ tau_p) {
    extern __shared__ char smem[];
    const uint32_t sb = smem_u32(smem);
    const int tid = threadIdx.x;
    const int wid = tid >> 5;
    const int lane = tid & 31;
    const int warp_m = wid & 3;
    const int warp_n = wid >> 2;
    const int rowbase = blockIdx.y * BM;
    const int colbase = blockIdx.x * BN;

    float acc[2][8][4];
#pragma unroll
    for (int mt = 0; mt < 2; ++mt)
#pragma unroll
        for (int nt = 0; nt < 8; ++nt)
#pragma unroll
            for (int e = 0; e < 4; ++e) acc[mt][nt][e] = 0.f;

    // Prologue: fill stages 0..2
#pragma unroll
    for (int s = 0; s < STAGES - 1; ++s) {
        fill_stage(sb + s * STAGE_BYTES, s, rowbase, colbase, tid);
        CP_COMMIT();
    }

    const int lr = lane & 15;            // ldmatrix row select
    const int lc = (lane >> 4) * 16;     // ldmatrix 16B col select

#pragma unroll 1
    for (int kc = 0; kc < NCH; ++kc) {
        CP_WAIT2();
        __syncthreads();
        // Issue next stage before compute
        if (kc + STAGES - 1 < NCH)
            fill_stage(sb + ((kc + STAGES - 1) & 3) * STAGE_BYTES,
                       kc + STAGES - 1, rowbase, colbase, tid);
        CP_COMMIT();

        const uint32_t sA = sb + (kc & 3) * STAGE_BYTES;
        const uint32_t sB = sA + 8192;
#pragma unroll
        for (int kk = 0; kk < 2; ++kk) {
            uint32_t a[2][4];
#pragma unroll
            for (int mt = 0; mt < 2; ++mt)
                ldsm_x4(a[mt][0], a[mt][1], a[mt][2], a[mt][3],
                        sA + sw64((uint32_t)((warp_m * 32 + mt * 16 + lr) * 64 + kk * 32 + lc)));
            uint32_t b[4][4];
#pragma unroll
            for (int np = 0; np < 4; ++np)
                ldsm_x4(b[np][0], b[np][1], b[np][2], b[np][3],
                        sB + sw64((uint32_t)((warp_n * 64 + np * 16 + lr) * 64 + kk * 32 + lc)));
#pragma unroll
            for (int mt = 0; mt < 2; ++mt)
#pragma unroll
                for (int nt = 0; nt < 8; ++nt)
                    mma16816(acc[mt][nt], a[mt], b[nt >> 1][nt & 1], b[nt >> 1][2 + (nt & 1)]);
        }
    }
    CP_WAIT0();
    __syncthreads();

    // ---------------- fused epilogue: logits -> online (m,Z,T) ----------------
    const float tau = *tau_p;
    const float two_tau = 2.0f * tau;
    const float dpen = -100.0f * tau;

    float tsq[16];
    const int cbn = colbase + warp_n * 64 + 2 * (lane & 3);
#pragma unroll
    for (int nt = 0; nt < 8; ++nt) {
        tsq[2 * nt]     = tau * g_sq[cbn + nt * 8];
        tsq[2 * nt + 1] = tau * g_sq[cbn + nt * 8 + 1];
    }

    float* sm_m = reinterpret_cast<float*>(smem);        // [128][4]
    float* sm_z = sm_m + 512;
    float* sm_t = sm_z + 512;

#pragma unroll
    for (int mt = 0; mt < 2; ++mt) {
#pragma unroll
        for (int hf = 0; hf < 2; ++hf) {
            const int rrow = warp_m * 32 + mt * 16 + (lane >> 2) + hf * 8;
            const int grow = rowbase + rrow;
            float lv[16];
            float cm = NEG_BIG;
#pragma unroll
            for (int nt = 0; nt < 8; ++nt) {
#pragma unroll
                for (int e = 0; e < 2; ++e) {
                    const int gcol = cbn + nt * 8 + e;
                    float l = fmaf(two_tau, acc[mt][nt][hf * 2 + e], -tsq[2 * nt + e]);
                    if (gcol == grow) l += dpen;
                    lv[2 * nt + e] = l;
                    cm = fmaxf(cm, l);
                }
            }
            float z = 0.f, tt = 0.f;
#pragma unroll
            for (int j = 0; j < 16; ++j) {
                float d = lv[j] - cm;
                float e = __expf(d);
                z += e;
                tt = fmaf(d, e, tt);
            }
            // reduce across the 4 lanes of the quad (same row)
#pragma unroll
            for (int o = 1; o < 4; o <<= 1) {
                float mo = __shfl_xor_sync(0xffffffffu, cm, o);
                float zo = __shfl_xor_sync(0xffffffffu, z,  o);
                float to = __shfl_xor_sync(0xffffffffu, tt, o);
                merge_stats(cm, z, tt, mo, zo, to);
            }
            if ((lane & 3) == 0) {
                sm_m[rrow * 4 + warp_n] = cm;
                sm_z[rrow * 4 + warp_n] = z;
                sm_t[rrow * 4 + warp_n] = tt;
            }
        }
    }
    __syncthreads();
    if (tid < BM) {
        float m = NEG_BIG, z = 0.f, tt = 0.f;
#pragma unroll
        for (int w = 0; w < 4; ++w)
            merge_stats(m, z, tt, sm_m[tid * 4 + w], sm_z[tid * 4 + w], sm_t[tid * 4 + w]);
        const int grow = rowbase + tid;
        g_pm[grow * NP + blockIdx.x] = m;
        g_pz[grow * NP + blockIdx.x] = z;
        g_pt[grow * NP + blockIdx.x] = tt;
    }
}

// ---------------------------------------------------------------------------
// Kernel 3: merge column partials -> entropy -> mean -> scale by coef
__global__ void finalize_kernel(const float* __restrict__ coef_p, float* __restrict__ out) {
    const int tid = threadIdx.x;
    float acc = 0.f;
    for (int rr = tid; rr < NN; rr += 1024) {
        float m = NEG_BIG, z = 0.f, t = 0.f;
#pragma unroll
        for (int s = 0; s < NP; ++s)
            merge_stats(m, z, t, g_pm[rr * NP + s], g_pz[rr * NP + s], g_pt[rr * NP + s]);
        acc += logf(z) - t / z;
    }
#pragma unroll
    for (int o = 16; o > 0; o >>= 1) acc += __shfl_down_sync(0xffffffffu, acc, o);
    __shared__ float ws[32];
    int wid = tid >> 5, lane = tid & 31;
    if (lane == 0) ws[wid] = acc;
    __syncthreads();
    if (tid == 0) {
        float tot = 0.f;
#pragma unroll
        for (int i = 0; i < 32; ++i) tot += ws[i];
        out[0] = coef_p[0] * (tot / (float)NN);
    }
}

// ---------------------------------------------------------------------------
extern "C" void kernel_launch(void* const* d_in, const int* in_sizes, int n_in,
                              void* d_out, int out_size) {
    (void)in_sizes; (void)n_in; (void)out_size;
    const float* x    = (const float*)d_in[0];
    const float* coef = (const float*)d_in[1];
    const float* tau  = (const float*)d_in[2];
    float* out = (float*)d_out;

    prep_kernel<<<NN, 192>>>(x);

    cudaFuncSetAttribute(main_kernel, cudaFuncAttributeMaxDynamicSharedMemorySize, SMEM_TOTAL);
    main_kernel<<<dim3(NN / BN, NN / BM), 512, SMEM_TOTAL>>>(tau);

    finalize_kernel<<<1, 1024>>>(coef, out);
}